// round 11
// baseline (speedup 1.0000x reference)
#include <cuda_runtime.h>
#include <cuda_bf16.h>

#define NG 8192
#define NC 4096
#define FGk 512
#define FCk 256
#define ALPHA 0.2f

typedef unsigned long long ull;

#define GG_CHUNKS (NG * (NG / 64))                  // 1048576
#define GCA_CHUNKS (NG * (NC / 64))                 // 524288
#define CC_CHUNKS (NC * (NC / 64))                  // 262144
#define TOT_CHUNKS (GG_CHUNKS + GCA_CHUNKS + CC_CHUNKS)

// ---------------- scratch (static device allocations) ----------------
__device__ float g_gene_h[NG * 64];
__device__ float g_cell_h[NC * 64];
__device__ __nv_bfloat16 g_gene_hTb[64 * NG];   // transposed bf16: [d][node]
__device__ __nv_bfloat16 g_cell_hTb[64 * NC];
// bit-packed adjacency (row-major, 64 cols per ull chunk)
__device__ ull g_bm_gg[GG_CHUNKS];
__device__ ull g_bm_gca[GCA_CHUNKS];
__device__ ull g_bm_cc[CC_CHUNKS];
// per-node exp pairs {exp(s), exp(ALPHA*s)} for each relation side
__device__ float2 g_e_gg1[NG], g_e_gg2[NG], g_e_gc1[NG], g_e_cg2[NG];
__device__ float2 g_e_cc1[NC], g_e_cc2[NC], g_e_gc2[NC], g_e_cg1[NC];
__device__ float g_gam_g[NG], g_gam_c[NC];
// unnormalized numerators / denominators (gg, cg split into 2 j-halves)
__device__ float g_Ngg0[NG * 64], g_Ngg1[NG * 64];
__device__ float g_lgg0[NG], g_lgg1[NG];
__device__ float g_Ngc[NG * 64], g_lgc[NG];
__device__ float g_Ncc[NC * 64], g_lcc[NC];
__device__ float g_Ncg0[NC * 64], g_Ncg1[NC * 64];
__device__ float g_lcg0[NC], g_lcg1[NC];

__device__ __forceinline__ float leaky(float x) { return x >= 0.f ? x : ALPHA * x; }

__device__ __forceinline__ void ldsm4(unsigned r[4], const void* p) {
    unsigned a = (unsigned)__cvta_generic_to_shared(p);
    asm volatile("ldmatrix.sync.aligned.m8n8.x4.shared.b16 {%0,%1,%2,%3}, [%4];"
                 : "=r"(r[0]), "=r"(r[1]), "=r"(r[2]), "=r"(r[3]) : "r"(a));
}

__device__ __forceinline__ void mma16816(float c[4], const unsigned a[4],
                                         unsigned b0, unsigned b1) {
    asm volatile(
        "mma.sync.aligned.m16n8k16.row.col.f32.bf16.bf16.f32 "
        "{%0,%1,%2,%3},{%4,%5,%6,%7},{%8,%9},{%0,%1,%2,%3};"
        : "+f"(c[0]), "+f"(c[1]), "+f"(c[2]), "+f"(c[3])
        : "r"(a[0]), "r"(a[1]), "r"(a[2]), "r"(a[3]), "r"(b0), "r"(b1));
}

__device__ __forceinline__ unsigned bf16x2(float lo, float hi) {
    unsigned r;
    asm("cvt.rn.bf16x2.f32 %0, %1, %2;" : "=r"(r) : "f"(hi), "f"(lo));
    return r;
}

// ---------------- adjacency bit-pack (448MB streamed once -> 14MB, L2-resident) ----
__global__ __launch_bounds__(256) void pack_kernel(const int* __restrict__ gadj,
                                                   const int* __restrict__ cadj,
                                                   const int* __restrict__ gca) {
    const int wgid = (blockIdx.x * 256 + threadIdx.x) >> 5;
    const int lane = threadIdx.x & 31;
    const int base = wgid * 64;
#pragma unroll 4
    for (int k = 0; k < 64; k++) {
        const int cid = base + k;
        const int* src;
        ull* dst;
        int W, c;
        if (cid < GG_CHUNKS) {
            src = gadj; dst = g_bm_gg; W = NG; c = cid;
        } else if (cid < GG_CHUNKS + GCA_CHUNKS) {
            src = gca; dst = g_bm_gca; W = NC; c = cid - GG_CHUNKS;
        } else {
            src = cadj; dst = g_bm_cc; W = NC; c = cid - GG_CHUNKS - GCA_CHUNKS;
        }
        const int chpr = W >> 6;                       // chunks per row
        const int row = c / chpr, ch = c - row * chpr;
        const int* p = src + (size_t)row * W + ch * 64;
        unsigned lo = __ballot_sync(0xFFFFFFFFu, __ldcs(p + lane) > 0);
        unsigned hi = __ballot_sync(0xFFFFFFFFu, __ldcs(p + lane + 32) > 0);
        if (lane == 0) dst[c] = (ull)lo | ((ull)hi << 32);
    }
}

// ---------------- feature GEMM: H[M,64] = X[M,K] @ W[K,64] (+ bf16 transposed copy) ----
__global__ void gemm64_kernel(const float* __restrict__ X, const float* __restrict__ W,
                              int K, int which) {
    __shared__ float xs[16 * FGk];
    float* H = which ? g_cell_h : g_gene_h;
    __nv_bfloat16* HT = which ? g_cell_hTb : g_gene_hTb;
    const int N = which ? NC : NG;
    const int m0 = blockIdx.x * 16;
    const int tid = threadIdx.x;

    const int nf4 = 16 * K / 4;
    const float4* src = (const float4*)(X + (size_t)m0 * K);
    float4* dst = (float4*)xs;
    for (int i = tid; i < nf4; i += 256) dst[i] = src[i];
    __syncthreads();

    const int d = tid & 63;
    const int rg = tid >> 6;
    float a0 = 0.f, a1 = 0.f, a2 = 0.f, a3 = 0.f;
    const float* xr = xs + (rg * 4) * K;
#pragma unroll 4
    for (int k = 0; k < K; k++) {
        float w = W[k * 64 + d];
        a0 += xr[k] * w;
        a1 += xr[K + k] * w;
        a2 += xr[2 * K + k] * w;
        a3 += xr[3 * K + k] * w;
    }
    const int row = m0 + rg * 4;
    H[(row + 0) * 64 + d] = a0;
    H[(row + 1) * 64 + d] = a1;
    H[(row + 2) * 64 + d] = a2;
    H[(row + 3) * 64 + d] = a3;
    HT[(size_t)d * N + row + 0] = __float2bfloat16(a0);
    HT[(size_t)d * N + row + 1] = __float2bfloat16(a1);
    HT[(size_t)d * N + row + 2] = __float2bfloat16(a2);
    HT[(size_t)d * N + row + 3] = __float2bfloat16(a3);
}

// ---------------- score vectors -> exp pairs + gates ----------------
__device__ __forceinline__ float warp_dot(float v0, float v1, const float* __restrict__ vec, int lane) {
    float t = v0 * vec[lane] + v1 * vec[lane + 32];
#pragma unroll
    for (int off = 16; off; off >>= 1) t += __shfl_xor_sync(0xFFFFFFFFu, t, off);
    return t;
}

__global__ void svec_kernel(const float* __restrict__ a_gg, const float* __restrict__ a_gc,
                            const float* __restrict__ a_cc, const float* __restrict__ a_cg,
                            const float* __restrict__ Wg, const float* __restrict__ bg,
                            const float* __restrict__ Wc, const float* __restrict__ bc) {
    const int w = blockIdx.x * 8 + (threadIdx.x >> 5);
    const int lane = threadIdx.x & 31;
    if (w < NG) {
        const float* h = g_gene_h + (size_t)w * 64;
        float v0 = h[lane], v1 = h[lane + 32];
        float d1 = warp_dot(v0, v1, a_gg, lane);
        float d2 = warp_dot(v0, v1, a_gg + 64, lane);
        float d3 = warp_dot(v0, v1, a_gc, lane);
        float d4 = warp_dot(v0, v1, a_cg + 64, lane);
        float dg = warp_dot(v0, v1, Wg, lane);
        if (lane == 0) {
            g_e_gg1[w] = make_float2(expf(d1), expf(ALPHA * d1));
            g_e_gg2[w] = make_float2(expf(d2), expf(ALPHA * d2));
            g_e_gc1[w] = make_float2(expf(d3), expf(ALPHA * d3));
            g_e_cg2[w] = make_float2(expf(d4), expf(ALPHA * d4));
            g_gam_g[w] = 1.0f / (1.0f + expf(-(dg + bg[0])));
        }
    } else if (w < NG + NC) {
        const int r = w - NG;
        const float* h = g_cell_h + (size_t)r * 64;
        float v0 = h[lane], v1 = h[lane + 32];
        float d1 = warp_dot(v0, v1, a_cc, lane);
        float d2 = warp_dot(v0, v1, a_cc + 64, lane);
        float d3 = warp_dot(v0, v1, a_gc + 64, lane);
        float d4 = warp_dot(v0, v1, a_cg, lane);
        float dg = warp_dot(v0, v1, Wc, lane);
        if (lane == 0) {
            g_e_cc1[r] = make_float2(expf(d1), expf(ALPHA * d1));
            g_e_cc2[r] = make_float2(expf(d2), expf(ALPHA * d2));
            g_e_gc2[r] = make_float2(expf(d3), expf(ALPHA * d3));
            g_e_cg1[r] = make_float2(expf(d4), expf(ALPHA * d4));
            g_gam_c[r] = 1.0f / (1.0f + expf(-(dg + bc[0])));
        }
    }
}

// tile prefetch into registers (bitmask + h + e2)
__device__ __forceinline__ void load_tile(bool trans, const ull* __restrict__ bm, int CH,
                                          const __nv_bfloat16* __restrict__ hTb,
                                          const float2* __restrict__ e2,
                                          int i0, int j0, int N,
                                          int tid, int r0, int c0,
                                          ull bmv[4], uint4 hv[2], float4 e2v[2]) {
    if (!trans) {
        const ull* bp = bm + (size_t)(i0 + r0) * CH + (j0 >> 6);
#pragma unroll
        for (int rr = 0; rr < 4; rr++) bmv[rr] = bp[(size_t)rr * CH];
    } else {
        const ull* bp = bm + (size_t)(j0 + c0) * CH + (i0 >> 6);
#pragma unroll
        for (int cc = 0; cc < 4; cc++) bmv[cc] = bp[(size_t)cc * CH];
    }
#pragma unroll
    for (int i = 0; i < 2; i++) {
        int s = tid + i * 256;              // 512 slots of 16B
        int d = s >> 3, ch = s & 7;
        hv[i] = *(const uint4*)&hTb[(size_t)d * N + j0 + ch * 8];
    }
    e2v[0] = *(const float4*)&e2[j0 + c0];
    e2v[1] = *(const float4*)&e2[j0 + c0 + 2];
}

// ---------------- fused relation kernel (bitmask adj + bf16 HMMA, 1 sync/tile) ----
// 576 uniform blocks, each: 64 src rows x 4096 dst cols (64 j-tiles of 64).
// [0,256) gg | [256,384) gc | [384,448) cc | [448,576) cg (transposed adj)
__global__ __launch_bounds__(256, 2) void rel_kernel() {
    __shared__ __nv_bfloat16 pshb[2][64 * 72];   // P tile [row][jj]
    __shared__ __nv_bfloat16 hshb[2][64 * 72];   // H^T tile [dim][jj]

    const int b = blockIdx.x;
    const float2 *e1, *e2;
    const __nv_bfloat16* hTb;
    const ull* bm;
    float *Nout, *lout;
    int i0, j0base, CH, Ndst;
    bool trans = false;
    if (b < 256) {
        i0 = (b >> 1) * 64; j0base = (b & 1) * 4096;
        e1 = g_e_gg1; e2 = g_e_gg2; hTb = g_gene_hTb; bm = g_bm_gg; CH = NG / 64; Ndst = NG;
        Nout = (b & 1) ? g_Ngg1 : g_Ngg0; lout = (b & 1) ? g_lgg1 : g_lgg0;
    } else if (b < 384) {
        i0 = (b - 256) * 64; j0base = 0;
        e1 = g_e_gc1; e2 = g_e_gc2; hTb = g_cell_hTb; bm = g_bm_gca; CH = NC / 64; Ndst = NC;
        Nout = g_Ngc; lout = g_lgc;
    } else if (b < 448) {
        i0 = (b - 384) * 64; j0base = 0;
        e1 = g_e_cc1; e2 = g_e_cc2; hTb = g_cell_hTb; bm = g_bm_cc; CH = NC / 64; Ndst = NC;
        Nout = g_Ncc; lout = g_lcc;
    } else {
        const int bb = b - 448;
        i0 = (bb >> 1) * 64; j0base = (bb & 1) * 4096;
        e1 = g_e_cg1; e2 = g_e_cg2; hTb = g_gene_hTb; bm = g_bm_gca; CH = NC / 64; Ndst = NG;
        trans = true;
        Nout = (bb & 1) ? g_Ncg1 : g_Ncg0; lout = (bb & 1) ? g_lcg1 : g_lcg0;
    }

    const int tid = threadIdx.x;
    const int tx = tid & 15;      // score col-group
    const int ty = tid >> 4;      // score row-group
    const int r0 = ty * 4, c0 = tx * 4;
    const int lane = tid & 31;
    const int wid = tid >> 5;
    const int rw = (wid & 3) * 16;        // mma C row offset
    const int dw = (wid >> 2) * 32;       // mma C dim offset

    float E1p[4], E1n[4];
#pragma unroll
    for (int rr = 0; rr < 4; rr++) {
        float2 v = e1[i0 + r0 + rr];
        E1p[rr] = v.x; E1n[rr] = v.y;
    }

    float cacc[4][4];
#pragma unroll
    for (int nb = 0; nb < 4; nb++)
#pragma unroll
        for (int q = 0; q < 4; q++) cacc[nb][q] = 0.f;
    float lp[4] = {0.f, 0.f, 0.f, 0.f};

    // prologue prefetch (tile 0)
    ull bmv[4]; uint4 hv[2]; float4 e2v[2];
    load_tile(trans, bm, CH, hTb, e2, i0, j0base, Ndst, tid, r0, c0, bmv, hv, e2v);

    for (int jt = 0; jt < 64; jt++) {
        const int buf = jt & 1;

        // H^T tile -> smem
#pragma unroll
        for (int i = 0; i < 2; i++) {
            int s = tid + i * 256;
            int d = s >> 3, ch = s & 7;
            *(uint4*)&hshb[buf][d * 72 + ch * 8] = hv[i];
        }

        // score -> bf16 P tile (+ exact fp32 denominator)
        float E2p[4], E2n[4];
        E2p[0] = e2v[0].x; E2n[0] = e2v[0].y; E2p[1] = e2v[0].z; E2n[1] = e2v[0].w;
        E2p[2] = e2v[1].x; E2n[2] = e2v[1].y; E2p[3] = e2v[1].z; E2n[3] = e2v[1].w;
#pragma unroll
        for (int rr = 0; rr < 4; rr++) {
            float pv[4];
#pragma unroll
            for (int cc = 0; cc < 4; cc++) {
                unsigned bit = trans ? (unsigned)(bmv[cc] >> (r0 + rr)) & 1u
                                     : (unsigned)(bmv[rr] >> (c0 + cc)) & 1u;
                float q = E1p[rr] * E2p[cc];
                float p = (q >= 1.f) ? q : E1n[rr] * E2n[cc];
                p = bit ? p : 0.f;
                pv[cc] = p;
                lp[rr] += p;
            }
            uint2 pk;
            pk.x = bf16x2(pv[0], pv[1]);
            pk.y = bf16x2(pv[2], pv[3]);
            *(uint2*)&pshb[buf][(r0 + rr) * 72 + c0] = pk;
        }

        // prefetch next tile (dummy-reload tile 0 on last iter)
        const int j0n = (jt < 63) ? j0base + (jt + 1) * 64 : j0base;
        load_tile(trans, bm, CH, hTb, e2, i0, j0n, Ndst, tid, r0, c0, bmv, hv, e2v);

        __syncthreads();   // pshb/hshb[buf] visible; prior mma on other buf finished earlier

        // ---- P @ H via HMMA: warp computes C[rw:rw+16][dw:dw+32] ----
        unsigned afr[4][4];
#pragma unroll
        for (int ks = 0; ks < 4; ks++)
            ldsm4(afr[ks], &pshb[buf][(rw + (lane & 15)) * 72 + ks * 16 + (lane >> 4) * 8]);
#pragma unroll
        for (int nb = 0; nb < 4; nb++) {
            unsigned b0[4], b1[4];
            const int nrow = dw + nb * 8 + (lane & 7);
            ldsm4(b0, &hshb[buf][nrow * 72 + (lane >> 3) * 8]);
            ldsm4(b1, &hshb[buf][nrow * 72 + 32 + (lane >> 3) * 8]);
            mma16816(cacc[nb], afr[0], b0[0], b0[1]);
            mma16816(cacc[nb], afr[1], b0[2], b0[3]);
            mma16816(cacc[nb], afr[2], b1[0], b1[1]);
            mma16816(cacc[nb], afr[3], b1[2], b1[3]);
        }
    }

    // ---- epilogue ----
#pragma unroll
    for (int rr = 0; rr < 4; rr++) {
        float v = lp[rr];
        v += __shfl_xor_sync(0xFFFFFFFFu, v, 1, 16);
        v += __shfl_xor_sync(0xFFFFFFFFu, v, 2, 16);
        v += __shfl_xor_sync(0xFFFFFFFFu, v, 4, 16);
        v += __shfl_xor_sync(0xFFFFFFFFu, v, 8, 16);
        lp[rr] = v;
    }
    if (tx == 0) {
#pragma unroll
        for (int rr = 0; rr < 4; rr++) lout[i0 + r0 + rr] = lp[rr];
    }
#pragma unroll
    for (int nb = 0; nb < 4; nb++) {
        const int r = i0 + rw + (lane >> 2);
        const int d = dw + nb * 8 + 2 * (lane & 3);
        *(float2*)&Nout[(size_t)r * 64 + d] = make_float2(cacc[nb][0], cacc[nb][1]);
        *(float2*)&Nout[(size_t)(r + 8) * 64 + d] = make_float2(cacc[nb][2], cacc[nb][3]);
    }
}

// ---------------- final combine (merge halves, normalize, gate, residual, leaky) ----
__global__ void combine_kernel(float* __restrict__ out) {
    const int idx4 = blockIdx.x * blockDim.x + threadIdx.x;
    const int e = idx4 * 4;
    if (e < NG * 64) {
        const int i = e >> 6;
        const float lg = g_lgg0[i] + g_lgg1[i];
        const float invgg = lg > 0.f ? 1.0f / lg : 0.f;
        const float lc = g_lgc[i];
        const float invgc = lc > 0.f ? 1.0f / lc : 0.f;
        const float ga = g_gam_g[i];
        float4 h = *(float4*)&g_gene_h[e];
        float4 A0 = *(float4*)&g_Ngg0[e];
        float4 A1 = *(float4*)&g_Ngg1[e];
        float4 B = *(float4*)&g_Ngc[e];
        float4 o;
        o.x = leaky(h.x + (A0.x + A1.x) * invgg + ga * B.x * invgc);
        o.y = leaky(h.y + (A0.y + A1.y) * invgg + ga * B.y * invgc);
        o.z = leaky(h.z + (A0.z + A1.z) * invgg + ga * B.z * invgc);
        o.w = leaky(h.w + (A0.w + A1.w) * invgg + ga * B.w * invgc);
        *(float4*)&out[e] = o;
    } else if (e < (NG + NC) * 64) {
        const int e2 = e - NG * 64;
        const int i = e2 >> 6;
        const float lcc_ = g_lcc[i];
        const float invcc = lcc_ > 0.f ? 1.0f / lcc_ : 0.f;
        const float lcg_ = g_lcg0[i] + g_lcg1[i];
        const float invcg = lcg_ > 0.f ? 1.0f / lcg_ : 0.f;
        const float gc_ = g_gam_c[i];
        float4 h = *(float4*)&g_cell_h[e2];
        float4 A = *(float4*)&g_Ncc[e2];
        float4 B0 = *(float4*)&g_Ncg0[e2];
        float4 B1 = *(float4*)&g_Ncg1[e2];
        float4 o;
        o.x = leaky(h.x + A.x * invcc + gc_ * (B0.x + B1.x) * invcg);
        o.y = leaky(h.y + A.y * invcc + gc_ * (B0.y + B1.y) * invcg);
        o.z = leaky(h.z + A.z * invcc + gc_ * (B0.z + B1.z) * invcg);
        o.w = leaky(h.w + A.w * invcc + gc_ * (B0.w + B1.w) * invcg);
        *(float4*)&out[e] = o;
    }
}

// ---------------- launch ----------------
extern "C" void kernel_launch(void* const* d_in, const int* in_sizes, int n_in,
                              void* d_out, int out_size) {
    const float* gene_x  = (const float*)d_in[0];
    const float* cell_x  = (const float*)d_in[1];
    const float* W_g     = (const float*)d_in[2];
    const float* W_c     = (const float*)d_in[3];
    const float* a_gg    = (const float*)d_in[4];
    const float* a_gc    = (const float*)d_in[5];
    const float* a_cc    = (const float*)d_in[6];
    const float* a_cg    = (const float*)d_in[7];
    const float* Wgate_g = (const float*)d_in[8];
    const float* bgate_g = (const float*)d_in[9];
    const float* Wgate_c = (const float*)d_in[10];
    const float* bgate_c = (const float*)d_in[11];
    const int* gene_adj  = (const int*)d_in[12];
    const int* cell_adj  = (const int*)d_in[13];
    const int* gca       = (const int*)d_in[14];
    float* out = (float*)d_out;

    pack_kernel<<<TOT_CHUNKS / (64 * 8), 256>>>(gene_adj, cell_adj, gca);
    gemm64_kernel<<<NG / 16, 256>>>(gene_x, W_g, FGk, 0);
    gemm64_kernel<<<NC / 16, 256>>>(cell_x, W_c, FCk, 1);
    svec_kernel<<<(NG + NC) / 8, 256>>>(a_gg, a_gc, a_cc, a_cg,
                                        Wgate_g, bgate_g, Wgate_c, bgate_c);
    rel_kernel<<<576, 256>>>();
    combine_kernel<<<((NG + NC) * 64 / 4) / 256, 256>>>(out);
}

// round 14
// speedup vs baseline: 1.0408x; 1.0408x over previous
#include <cuda_runtime.h>
#include <cuda_bf16.h>

#define NG 8192
#define NC 4096
#define FGk 512
#define FCk 256
#define ALPHA 0.2f

typedef unsigned long long ull;

#define GG_CHUNKS (NG * (NG / 64))
#define GCA_CHUNKS (NG * (NC / 64))
#define CC_CHUNKS (NC * (NC / 64))
#define TOT_CHUNKS (GG_CHUNKS + GCA_CHUNKS + CC_CHUNKS)

// ---------------- scratch ----------------
__device__ float g_gene_h[NG * 64];
__device__ float g_cell_h[NC * 64];
__device__ __nv_bfloat16 g_gene_hTb[64 * NG];   // transposed bf16: [d][node]
__device__ __nv_bfloat16 g_cell_hTb[64 * NC];
__device__ ull g_bm_gg[GG_CHUNKS];
__device__ ull g_bm_gca[GCA_CHUNKS];
__device__ ull g_bm_cc[CC_CHUNKS];
// bf16 exp factors: src side {e^s, e^(a s)} packed; dst side separate p/n arrays
__device__ __nv_bfloat162 g_b1_gg[NG], g_b1_gc[NG];
__device__ __nv_bfloat162 g_b1_cc[NC], g_b1_cg[NC];
__device__ __nv_bfloat16 g_b2p_gg[NG], g_b2n_gg[NG];
__device__ __nv_bfloat16 g_b2p_cg[NG], g_b2n_cg[NG];   // cg dst = gene
__device__ __nv_bfloat16 g_b2p_gc[NC], g_b2n_gc[NC];   // gc dst = cell
__device__ __nv_bfloat16 g_b2p_cc[NC], g_b2n_cc[NC];
__device__ float g_gam_g[NG], g_gam_c[NC];
// numerators / denominators (gg, cg split into 2 j-halves)
__device__ float g_Ngg0[NG * 64], g_Ngg1[NG * 64];
__device__ float g_lgg0[NG], g_lgg1[NG];
__device__ float g_Ngc[NG * 64], g_lgc[NG];
__device__ float g_Ncc[NC * 64], g_lcc[NC];
__device__ float g_Ncg0[NC * 64], g_Ncg1[NC * 64];
__device__ float g_lcg0[NC], g_lcg1[NC];

__device__ __forceinline__ float leaky(float x) { return x >= 0.f ? x : ALPHA * x; }

__device__ __forceinline__ void ldsm4(unsigned r[4], const void* p) {
    unsigned a = (unsigned)__cvta_generic_to_shared(p);
    asm volatile("ldmatrix.sync.aligned.m8n8.x4.shared.b16 {%0,%1,%2,%3}, [%4];"
                 : "=r"(r[0]), "=r"(r[1]), "=r"(r[2]), "=r"(r[3]) : "r"(a));
}

__device__ __forceinline__ void mma16816(float c[4], const unsigned a[4],
                                         unsigned b0, unsigned b1) {
    asm volatile(
        "mma.sync.aligned.m16n8k16.row.col.f32.bf16.bf16.f32 "
        "{%0,%1,%2,%3},{%4,%5,%6,%7},{%8,%9},{%0,%1,%2,%3};"
        : "+f"(c[0]), "+f"(c[1]), "+f"(c[2]), "+f"(c[3])
        : "r"(a[0]), "r"(a[1]), "r"(a[2]), "r"(a[3]), "r"(b0), "r"(b1));
}

#define CP16(dst_u32, src_ptr) \
    asm volatile("cp.async.cg.shared.global [%0], [%1], 16;" :: "r"(dst_u32), "l"(src_ptr))
#define CP_COMMIT() asm volatile("cp.async.commit_group;")
#define CP_WAIT0()  asm volatile("cp.async.wait_group 0;" ::: "memory")

// ---------------- adjacency bit-pack (448MB streamed once -> 14MB) ----------------
__global__ __launch_bounds__(256) void pack_kernel(const int* __restrict__ gadj,
                                                   const int* __restrict__ cadj,
                                                   const int* __restrict__ gca) {
    const int wgid = (blockIdx.x * 256 + threadIdx.x) >> 5;
    const int lane = threadIdx.x & 31;
    const int base = wgid * 64;
#pragma unroll 8
    for (int k = 0; k < 64; k++) {
        const int cid = base + k;
        const int* src;
        ull* dst;
        int W, c;
        if (cid < GG_CHUNKS) {
            src = gadj; dst = g_bm_gg; W = NG; c = cid;
        } else if (cid < GG_CHUNKS + GCA_CHUNKS) {
            src = gca; dst = g_bm_gca; W = NC; c = cid - GG_CHUNKS;
        } else {
            src = cadj; dst = g_bm_cc; W = NC; c = cid - GG_CHUNKS - GCA_CHUNKS;
        }
        const int chpr = W >> 6;
        const int row = c / chpr, ch = c - row * chpr;
        const int* p = src + (size_t)row * W + ch * 64;
        unsigned lo = __ballot_sync(0xFFFFFFFFu, __ldcs(p + lane) > 0);
        unsigned hi = __ballot_sync(0xFFFFFFFFu, __ldcs(p + lane + 32) > 0);
        if (lane == 0) dst[c] = (ull)lo | ((ull)hi << 32);
    }
}

// ---------------- feature GEMM: H = X @ W (+ bf16 transposed copy) ----------------
__global__ void gemm64_kernel(const float* __restrict__ X, const float* __restrict__ W,
                              int K, int which) {
    __shared__ float xs[16 * FGk];
    float* H = which ? g_cell_h : g_gene_h;
    __nv_bfloat16* HT = which ? g_cell_hTb : g_gene_hTb;
    const int N = which ? NC : NG;
    const int m0 = blockIdx.x * 16;
    const int tid = threadIdx.x;

    const int nf4 = 16 * K / 4;
    const float4* src = (const float4*)(X + (size_t)m0 * K);
    float4* dst = (float4*)xs;
    for (int i = tid; i < nf4; i += 256) dst[i] = src[i];
    __syncthreads();

    const int d = tid & 63;
    const int rg = tid >> 6;
    float a0 = 0.f, a1 = 0.f, a2 = 0.f, a3 = 0.f;
    const float* xr = xs + (rg * 4) * K;
#pragma unroll 4
    for (int k = 0; k < K; k++) {
        float w = W[k * 64 + d];
        a0 += xr[k] * w;
        a1 += xr[K + k] * w;
        a2 += xr[2 * K + k] * w;
        a3 += xr[3 * K + k] * w;
    }
    const int row = m0 + rg * 4;
    H[(row + 0) * 64 + d] = a0;
    H[(row + 1) * 64 + d] = a1;
    H[(row + 2) * 64 + d] = a2;
    H[(row + 3) * 64 + d] = a3;
    HT[(size_t)d * N + row + 0] = __float2bfloat16(a0);
    HT[(size_t)d * N + row + 1] = __float2bfloat16(a1);
    HT[(size_t)d * N + row + 2] = __float2bfloat16(a2);
    HT[(size_t)d * N + row + 3] = __float2bfloat16(a3);
}

// ---------------- score vectors -> bf16 exp factors + gates ----------------
__device__ __forceinline__ float warp_dot(float v0, float v1, const float* __restrict__ vec, int lane) {
    float t = v0 * vec[lane] + v1 * vec[lane + 32];
#pragma unroll
    for (int off = 16; off; off >>= 1) t += __shfl_xor_sync(0xFFFFFFFFu, t, off);
    return t;
}

__global__ void svec_kernel(const float* __restrict__ a_gg, const float* __restrict__ a_gc,
                            const float* __restrict__ a_cc, const float* __restrict__ a_cg,
                            const float* __restrict__ Wg, const float* __restrict__ bg,
                            const float* __restrict__ Wc, const float* __restrict__ bc) {
    const int w = blockIdx.x * 8 + (threadIdx.x >> 5);
    const int lane = threadIdx.x & 31;
    if (w < NG) {
        const float* h = g_gene_h + (size_t)w * 64;
        float v0 = h[lane], v1 = h[lane + 32];
        float d1 = warp_dot(v0, v1, a_gg, lane);
        float d2 = warp_dot(v0, v1, a_gg + 64, lane);
        float d3 = warp_dot(v0, v1, a_gc, lane);
        float d4 = warp_dot(v0, v1, a_cg + 64, lane);
        float dg = warp_dot(v0, v1, Wg, lane);
        if (lane == 0) {
            g_b1_gg[w] = __floats2bfloat162_rn(expf(d1), expf(ALPHA * d1));
            g_b2p_gg[w] = __float2bfloat16(expf(d2));
            g_b2n_gg[w] = __float2bfloat16(expf(ALPHA * d2));
            g_b1_gc[w] = __floats2bfloat162_rn(expf(d3), expf(ALPHA * d3));
            g_b2p_cg[w] = __float2bfloat16(expf(d4));
            g_b2n_cg[w] = __float2bfloat16(expf(ALPHA * d4));
            g_gam_g[w] = 1.0f / (1.0f + expf(-(dg + bg[0])));
        }
    } else if (w < NG + NC) {
        const int r = w - NG;
        const float* h = g_cell_h + (size_t)r * 64;
        float v0 = h[lane], v1 = h[lane + 32];
        float d1 = warp_dot(v0, v1, a_cc, lane);
        float d2 = warp_dot(v0, v1, a_cc + 64, lane);
        float d3 = warp_dot(v0, v1, a_gc + 64, lane);
        float d4 = warp_dot(v0, v1, a_cg, lane);
        float dg = warp_dot(v0, v1, Wc, lane);
        if (lane == 0) {
            g_b1_cc[r] = __floats2bfloat162_rn(expf(d1), expf(ALPHA * d1));
            g_b2p_cc[r] = __float2bfloat16(expf(d2));
            g_b2n_cc[r] = __float2bfloat16(expf(ALPHA * d2));
            g_b2p_gc[r] = __float2bfloat16(expf(d3));
            g_b2n_gc[r] = __float2bfloat16(expf(ALPHA * d3));
            g_b1_cg[r] = __floats2bfloat162_rn(expf(d4), expf(ALPHA * d4));
            g_gam_c[r] = 1.0f / (1.0f + expf(-(dg + bc[0])));
        }
    }
}

// small per-tile loads (bitmask rows + dst exp factors)
__device__ __forceinline__ void load_be(bool trans, const ull* __restrict__ bm, int CH,
                                        const __nv_bfloat16* __restrict__ b2p,
                                        const __nv_bfloat16* __restrict__ b2n,
                                        int i0, int j0, int r0, int c0,
                                        ull bmv[4], uint2& e2pu, uint2& e2nu) {
    if (!trans) {
        const ull* bp = bm + (size_t)(i0 + r0) * CH + (j0 >> 6);
#pragma unroll
        for (int rr = 0; rr < 4; rr++) bmv[rr] = bp[(size_t)rr * CH];
    } else {
        const ull* bp = bm + (size_t)(j0 + c0) * CH + (i0 >> 6);
#pragma unroll
        for (int cc = 0; cc < 4; cc++) bmv[cc] = bp[(size_t)cc * CH];
    }
    e2pu = *(const uint2*)&b2p[j0 + c0];
    e2nu = *(const uint2*)&b2n[j0 + c0];
}

// ---------------- fused relation kernel ----------------
// 576 blocks: [0,256) gg | [256,384) gc | [384,448) cc | [448,576) cg (transposed)
__global__ __launch_bounds__(256, 3) void rel_kernel() {
    __shared__ __nv_bfloat16 pshb[2][64 * 72];   // P [row][jj]
    __shared__ __nv_bfloat16 hshb[2][72 * 72];   // H^T [n-row][jj]; rows 64..71: ones/zero

    const int b = blockIdx.x;
    const __nv_bfloat162* b1;
    const __nv_bfloat16 *b2p, *b2n, *hTb;
    const ull* bm;
    float *Nout, *lout;
    int i0, j0base, CH, Ndst;
    bool trans = false;
    if (b < 256) {
        i0 = (b >> 1) * 64; j0base = (b & 1) * 4096;
        b1 = g_b1_gg; b2p = g_b2p_gg; b2n = g_b2n_gg; hTb = g_gene_hTb;
        bm = g_bm_gg; CH = NG / 64; Ndst = NG;
        Nout = (b & 1) ? g_Ngg1 : g_Ngg0; lout = (b & 1) ? g_lgg1 : g_lgg0;
    } else if (b < 384) {
        i0 = (b - 256) * 64; j0base = 0;
        b1 = g_b1_gc; b2p = g_b2p_gc; b2n = g_b2n_gc; hTb = g_cell_hTb;
        bm = g_bm_gca; CH = NC / 64; Ndst = NC;
        Nout = g_Ngc; lout = g_lgc;
    } else if (b < 448) {
        i0 = (b - 384) * 64; j0base = 0;
        b1 = g_b1_cc; b2p = g_b2p_cc; b2n = g_b2n_cc; hTb = g_cell_hTb;
        bm = g_bm_cc; CH = NC / 64; Ndst = NC;
        Nout = g_Ncc; lout = g_lcc;
    } else {
        const int bb = b - 448;
        i0 = (bb >> 1) * 64; j0base = (bb & 1) * 4096;
        b1 = g_b1_cg; b2p = g_b2p_cg; b2n = g_b2n_cg; hTb = g_gene_hTb;
        bm = g_bm_gca; CH = NC / 64; Ndst = NG; trans = true;
        Nout = (bb & 1) ? g_Ncg1 : g_Ncg0; lout = (bb & 1) ? g_lcg1 : g_lcg0;
    }

    const int tid = threadIdx.x;
    const int tx = tid & 15, ty = tid >> 4;
    const int r0 = ty * 4, c0 = tx * 4;
    const int lane = tid & 31, wid = tid >> 5;
    const int rw = (wid & 3) * 16;
    const int wgrp = wid >> 2;            // 0: n=[0,40), 1: n=[40,72)

    // hoisted src-side factors (duplicated bf16x2)
    __nv_bfloat162 E1p2[4], E1n2[4];
#pragma unroll
    for (int rr = 0; rr < 4; rr++) {
        __nv_bfloat162 t = b1[i0 + r0 + rr];
        E1p2[rr] = __bfloat162bfloat162(__low2bfloat16(t));
        E1n2[rr] = __bfloat162bfloat162(__high2bfloat16(t));
    }
    const __nv_bfloat162 one2 = __floats2bfloat162_rn(1.f, 1.f);

    // ones/zero rows 64..71 in both h buffers (row 64 = 1.0 -> denominator column)
    {
        const __nv_bfloat16 onev = __float2bfloat16(1.f);
        const __nv_bfloat16 zerov = __float2bfloat16(0.f);
        for (int s = tid; s < 8 * 72; s += 256) {
            int r = 64 + s / 72, j = s % 72;
            __nv_bfloat16 v = (r == 64) ? onev : zerov;
            hshb[0][r * 72 + j] = v;
            hshb[1][r * 72 + j] = v;
        }
    }

    const int d1 = tid >> 3, ch1 = tid & 7;      // slot 1
    const int d2 = d1 + 32, ch2 = ch1;           // slot 2
    // prologue: h(0) via cp.async
    CP16((unsigned)__cvta_generic_to_shared(&hshb[0][d1 * 72 + ch1 * 8]),
         &hTb[(size_t)d1 * Ndst + j0base + ch1 * 8]);
    CP16((unsigned)__cvta_generic_to_shared(&hshb[0][d2 * 72 + ch2 * 8]),
         &hTb[(size_t)d2 * Ndst + j0base + ch2 * 8]);
    CP_COMMIT();

    ull bmv[4]; uint2 e2pu, e2nu;
    load_be(trans, bm, CH, b2p, b2n, i0, j0base, r0, c0, bmv, e2pu, e2nu);

    float cacc[5][4];
#pragma unroll
    for (int nb = 0; nb < 5; nb++)
#pragma unroll
        for (int q = 0; q < 4; q++) cacc[nb][q] = 0.f;

    for (int jt = 0; jt < 64; jt++) {
        const int buf = jt & 1;

        // ---- score -> bf16 P tile ----
#pragma unroll
        for (int rr = 0; rr < 4; rr++) {
            unsigned outw[2];
#pragma unroll
            for (int q = 0; q < 2; q++) {
                __nv_bfloat162 e2pp = ((const __nv_bfloat162*)&e2pu)[q];
                __nv_bfloat162 e2nn = ((const __nv_bfloat162*)&e2nu)[q];
                __nv_bfloat162 q2 = __hmul2(E1p2[rr], e2pp);
                __nv_bfloat162 n2 = __hmul2(E1n2[rr], e2nn);
                __nv_bfloat162 m2 = __hge2(q2, one2);
                __nv_bfloat162 p2 = __hfma2(m2, __hsub2(q2, n2), n2);
                unsigned pu = *(unsigned*)&p2;
                unsigned sel;
                if (!trans) sel = (unsigned)(bmv[rr] >> (c0 + 2 * q)) & 3u;
                else sel = ((unsigned)(bmv[2 * q] >> (r0 + rr)) & 1u) |
                           (((unsigned)(bmv[2 * q + 1] >> (r0 + rr)) & 1u) << 1);
                unsigned msk = ((sel & 1u) ? 0x0000FFFFu : 0u) | ((sel & 2u) ? 0xFFFF0000u : 0u);
                outw[q] = pu & msk;
            }
            *(uint2*)&pshb[buf][(r0 + rr) * 72 + c0] = make_uint2(outw[0], outw[1]);
        }

        // prefetch small next-tile data
        const int j0n = j0base + ((jt < 63) ? (jt + 1) : 0) * 64;
        ull bmn[4]; uint2 e2pn, e2nn2;
        load_be(trans, bm, CH, b2p, b2n, i0, j0n, r0, c0, bmn, e2pn, e2nn2);

        CP_WAIT0();          // h(jt) landed
        __syncthreads();     // P tile + everyone past mma(jt-1)

        // issue h(jt+1) into the other buffer (overlaps with mma + next score)
        if (jt < 63) {
            const int jh = j0base + (jt + 1) * 64;
            CP16((unsigned)__cvta_generic_to_shared(&hshb[buf ^ 1][d1 * 72 + ch1 * 8]),
                 &hTb[(size_t)d1 * Ndst + jh + ch1 * 8]);
            CP16((unsigned)__cvta_generic_to_shared(&hshb[buf ^ 1][d2 * 72 + ch2 * 8]),
                 &hTb[(size_t)d2 * Ndst + jh + ch2 * 8]);
            CP_COMMIT();
        }

        // ---- P @ [H; ones] via HMMA ----
        unsigned afr[4][4];
#pragma unroll
        for (int ks = 0; ks < 4; ks++)
            ldsm4(afr[ks], &pshb[buf][(rw + (lane & 15)) * 72 + ks * 16 + (lane >> 4) * 8]);
        if (wgrp == 0) {
#pragma unroll
            for (int nb = 0; nb < 5; nb++) {
                unsigned b0[4], b1f[4];
                const int nrow = nb * 8 + (lane & 7);
                ldsm4(b0, &hshb[buf][nrow * 72 + (lane >> 3) * 8]);
                ldsm4(b1f, &hshb[buf][nrow * 72 + 32 + (lane >> 3) * 8]);
                mma16816(cacc[nb], afr[0], b0[0], b0[1]);
                mma16816(cacc[nb], afr[1], b0[2], b0[3]);
                mma16816(cacc[nb], afr[2], b1f[0], b1f[1]);
                mma16816(cacc[nb], afr[3], b1f[2], b1f[3]);
            }
        } else {
#pragma unroll
            for (int nb = 0; nb < 4; nb++) {
                unsigned b0[4], b1f[4];
                const int nrow = 40 + nb * 8 + (lane & 7);
                ldsm4(b0, &hshb[buf][nrow * 72 + (lane >> 3) * 8]);
                ldsm4(b1f, &hshb[buf][nrow * 72 + 32 + (lane >> 3) * 8]);
                mma16816(cacc[nb], afr[0], b0[0], b0[1]);
                mma16816(cacc[nb], afr[1], b0[2], b0[3]);
                mma16816(cacc[nb], afr[2], b1f[0], b1f[1]);
                mma16816(cacc[nb], afr[3], b1f[2], b1f[3]);
            }
        }

#pragma unroll
        for (int rr = 0; rr < 4; rr++) bmv[rr] = bmn[rr];
        e2pu = e2pn; e2nu = e2nn2;
    }

    // ---- epilogue: store N (cols 0..63) and l (ones column = col 64) ----
    const int crow = i0 + rw + (lane >> 2);
    if (wgrp == 0) {
#pragma unroll
        for (int nb = 0; nb < 5; nb++) {
            const int d = nb * 8 + 2 * (lane & 3);
            *(float2*)&Nout[(size_t)crow * 64 + d] = make_float2(cacc[nb][0], cacc[nb][1]);
            *(float2*)&Nout[(size_t)(crow + 8) * 64 + d] = make_float2(cacc[nb][2], cacc[nb][3]);
        }
    } else {
#pragma unroll
        for (int nb = 0; nb < 3; nb++) {
            const int d = 40 + nb * 8 + 2 * (lane & 3);
            *(float2*)&Nout[(size_t)crow * 64 + d] = make_float2(cacc[nb][0], cacc[nb][1]);
            *(float2*)&Nout[(size_t)(crow + 8) * 64 + d] = make_float2(cacc[nb][2], cacc[nb][3]);
        }
        if ((lane & 3) == 0) {           // col 64 = denominator
            lout[crow] = cacc[3][0];
            lout[crow + 8] = cacc[3][2];
        }
    }
}

// ---------------- final combine ----------------
__global__ void combine_kernel(float* __restrict__ out) {
    const int idx4 = blockIdx.x * blockDim.x + threadIdx.x;
    const int e = idx4 * 4;
    if (e < NG * 64) {
        const int i = e >> 6;
        const float lg = g_lgg0[i] + g_lgg1[i];
        const float invgg = lg > 0.f ? 1.0f / lg : 0.f;
        const float lc = g_lgc[i];
        const float invgc = lc > 0.f ? 1.0f / lc : 0.f;
        const float ga = g_gam_g[i];
        float4 h = *(float4*)&g_gene_h[e];
        float4 A0 = *(float4*)&g_Ngg0[e];
        float4 A1 = *(float4*)&g_Ngg1[e];
        float4 B = *(float4*)&g_Ngc[e];
        float4 o;
        o.x = leaky(h.x + (A0.x + A1.x) * invgg + ga * B.x * invgc);
        o.y = leaky(h.y + (A0.y + A1.y) * invgg + ga * B.y * invgc);
        o.z = leaky(h.z + (A0.z + A1.z) * invgg + ga * B.z * invgc);
        o.w = leaky(h.w + (A0.w + A1.w) * invgg + ga * B.w * invgc);
        *(float4*)&out[e] = o;
    } else if (e < (NG + NC) * 64) {
        const int e2 = e - NG * 64;
        const int i = e2 >> 6;
        const float lcc_ = g_lcc[i];
        const float invcc = lcc_ > 0.f ? 1.0f / lcc_ : 0.f;
        const float lcg_ = g_lcg0[i] + g_lcg1[i];
        const float invcg = lcg_ > 0.f ? 1.0f / lcg_ : 0.f;
        const float gc_ = g_gam_c[i];
        float4 h = *(float4*)&g_cell_h[e2];
        float4 A = *(float4*)&g_Ncc[e2];
        float4 B0 = *(float4*)&g_Ncg0[e2];
        float4 B1 = *(float4*)&g_Ncg1[e2];
        float4 o;
        o.x = leaky(h.x + A.x * invcc + gc_ * (B0.x + B1.x) * invcg);
        o.y = leaky(h.y + A.y * invcc + gc_ * (B0.y + B1.y) * invcg);
        o.z = leaky(h.z + A.z * invcc + gc_ * (B0.z + B1.z) * invcg);
        o.w = leaky(h.w + A.w * invcc + gc_ * (B0.w + B1.w) * invcg);
        *(float4*)&out[e] = o;
    }
}

// ---------------- launch ----------------
extern "C" void kernel_launch(void* const* d_in, const int* in_sizes, int n_in,
                              void* d_out, int out_size) {
    const float* gene_x  = (const float*)d_in[0];
    const float* cell_x  = (const float*)d_in[1];
    const float* W_g     = (const float*)d_in[2];
    const float* W_c     = (const float*)d_in[3];
    const float* a_gg    = (const float*)d_in[4];
    const float* a_gc    = (const float*)d_in[5];
    const float* a_cc    = (const float*)d_in[6];
    const float* a_cg    = (const float*)d_in[7];
    const float* Wgate_g = (const float*)d_in[8];
    const float* bgate_g = (const float*)d_in[9];
    const float* Wgate_c = (const float*)d_in[10];
    const float* bgate_c = (const float*)d_in[11];
    const int* gene_adj  = (const int*)d_in[12];
    const int* cell_adj  = (const int*)d_in[13];
    const int* gca       = (const int*)d_in[14];
    float* out = (float*)d_out;

    pack_kernel<<<TOT_CHUNKS / (64 * 8), 256>>>(gene_adj, cell_adj, gca);
    gemm64_kernel<<<NG / 16, 256>>>(gene_x, W_g, FGk, 0);
    gemm64_kernel<<<NC / 16, 256>>>(cell_x, W_c, FCk, 1);
    svec_kernel<<<(NG + NC) / 8, 256>>>(a_gg, a_gc, a_cc, a_cg,
                                        Wgate_g, bgate_g, Wgate_c, bgate_c);
    rel_kernel<<<576, 256>>>();
    combine_kernel<<<((NG + NC) * 64 / 4) / 256, 256>>>(out);
}

// round 15
// speedup vs baseline: 1.2950x; 1.2443x over previous
#include <cuda_runtime.h>
#include <cuda_bf16.h>

#define NG 8192
#define NC 4096
#define FGk 512
#define FCk 256
#define ALPHA 0.2f

typedef unsigned long long ull;

// ---------------- scratch ----------------
__device__ float g_gene_h[NG * 64];
__device__ float g_cell_h[NC * 64];
__device__ __nv_bfloat16 g_gene_hTb[64 * NG];   // transposed bf16: [d][node]
__device__ __nv_bfloat16 g_cell_hTb[64 * NC];
// per-node exp pairs {exp(s), exp(ALPHA*s)} for each relation side (fp32)
__device__ float2 g_e_gg1[NG], g_e_gg2[NG], g_e_gc1[NG], g_e_cg2[NG];
__device__ float2 g_e_cc1[NC], g_e_cc2[NC], g_e_gc2[NC], g_e_cg1[NC];
__device__ float g_gam_g[NG], g_gam_c[NC];
// numerators / denominators (gg, cg split into 2 j-halves)
__device__ float g_Ngg0[NG * 64], g_Ngg1[NG * 64];
__device__ float g_lgg0[NG], g_lgg1[NG];
__device__ float g_Ngc[NG * 64], g_lgc[NG];
__device__ float g_Ncc[NC * 64], g_lcc[NC];
__device__ float g_Ncg0[NC * 64], g_Ncg1[NC * 64];
__device__ float g_lcg0[NC], g_lcg1[NC];

__device__ __forceinline__ float leaky(float x) { return x >= 0.f ? x : ALPHA * x; }

__device__ __forceinline__ void ldsm4(unsigned r[4], const void* p) {
    unsigned a = (unsigned)__cvta_generic_to_shared(p);
    asm volatile("ldmatrix.sync.aligned.m8n8.x4.shared.b16 {%0,%1,%2,%3}, [%4];"
                 : "=r"(r[0]), "=r"(r[1]), "=r"(r[2]), "=r"(r[3]) : "r"(a));
}

__device__ __forceinline__ void mma16816(float c[4], const unsigned a[4],
                                         unsigned b0, unsigned b1) {
    asm volatile(
        "mma.sync.aligned.m16n8k16.row.col.f32.bf16.bf16.f32 "
        "{%0,%1,%2,%3},{%4,%5,%6,%7},{%8,%9},{%0,%1,%2,%3};"
        : "+f"(c[0]), "+f"(c[1]), "+f"(c[2]), "+f"(c[3])
        : "r"(a[0]), "r"(a[1]), "r"(a[2]), "r"(a[3]), "r"(b0), "r"(b1));
}

__device__ __forceinline__ unsigned bf16x2(float lo, float hi) {
    unsigned r;
    asm("cvt.rn.bf16x2.f32 %0, %1, %2;" : "=r"(r) : "f"(hi), "f"(lo));
    return r;
}

#define CP16(dst_u32, src_ptr) \
    asm volatile("cp.async.cg.shared.global [%0], [%1], 16;" :: "r"(dst_u32), "l"(src_ptr))
#define CP_COMMIT() asm volatile("cp.async.commit_group;")
#define CP_WAIT0()  asm volatile("cp.async.wait_group 0;" ::: "memory")

// ---------------- feature GEMM: H = X @ W (+ bf16 transposed copy) ----------------
__global__ void gemm64_kernel(const float* __restrict__ X, const float* __restrict__ W,
                              int K, int which) {
    __shared__ float xs[16 * FGk];
    float* H = which ? g_cell_h : g_gene_h;
    __nv_bfloat16* HT = which ? g_cell_hTb : g_gene_hTb;
    const int N = which ? NC : NG;
    const int m0 = blockIdx.x * 16;
    const int tid = threadIdx.x;

    const int nf4 = 16 * K / 4;
    const float4* src = (const float4*)(X + (size_t)m0 * K);
    float4* dst = (float4*)xs;
    for (int i = tid; i < nf4; i += 256) dst[i] = src[i];
    __syncthreads();

    const int d = tid & 63;
    const int rg = tid >> 6;
    float a0 = 0.f, a1 = 0.f, a2 = 0.f, a3 = 0.f;
    const float* xr = xs + (rg * 4) * K;
#pragma unroll 4
    for (int k = 0; k < K; k++) {
        float w = W[k * 64 + d];
        a0 += xr[k] * w;
        a1 += xr[K + k] * w;
        a2 += xr[2 * K + k] * w;
        a3 += xr[3 * K + k] * w;
    }
    const int row = m0 + rg * 4;
    H[(row + 0) * 64 + d] = a0;
    H[(row + 1) * 64 + d] = a1;
    H[(row + 2) * 64 + d] = a2;
    H[(row + 3) * 64 + d] = a3;
    HT[(size_t)d * N + row + 0] = __float2bfloat16(a0);
    HT[(size_t)d * N + row + 1] = __float2bfloat16(a1);
    HT[(size_t)d * N + row + 2] = __float2bfloat16(a2);
    HT[(size_t)d * N + row + 3] = __float2bfloat16(a3);
}

// ---------------- score vectors -> exp pairs + gates ----------------
__device__ __forceinline__ float warp_dot(float v0, float v1, const float* __restrict__ vec, int lane) {
    float t = v0 * vec[lane] + v1 * vec[lane + 32];
#pragma unroll
    for (int off = 16; off; off >>= 1) t += __shfl_xor_sync(0xFFFFFFFFu, t, off);
    return t;
}

__global__ void svec_kernel(const float* __restrict__ a_gg, const float* __restrict__ a_gc,
                            const float* __restrict__ a_cc, const float* __restrict__ a_cg,
                            const float* __restrict__ Wg, const float* __restrict__ bg,
                            const float* __restrict__ Wc, const float* __restrict__ bc) {
    const int w = blockIdx.x * 8 + (threadIdx.x >> 5);
    const int lane = threadIdx.x & 31;
    if (w < NG) {
        const float* h = g_gene_h + (size_t)w * 64;
        float v0 = h[lane], v1 = h[lane + 32];
        float d1 = warp_dot(v0, v1, a_gg, lane);
        float d2 = warp_dot(v0, v1, a_gg + 64, lane);
        float d3 = warp_dot(v0, v1, a_gc, lane);
        float d4 = warp_dot(v0, v1, a_cg + 64, lane);
        float dg = warp_dot(v0, v1, Wg, lane);
        if (lane == 0) {
            g_e_gg1[w] = make_float2(expf(d1), expf(ALPHA * d1));
            g_e_gg2[w] = make_float2(expf(d2), expf(ALPHA * d2));
            g_e_gc1[w] = make_float2(expf(d3), expf(ALPHA * d3));
            g_e_cg2[w] = make_float2(expf(d4), expf(ALPHA * d4));
            g_gam_g[w] = 1.0f / (1.0f + expf(-(dg + bg[0])));
        }
    } else if (w < NG + NC) {
        const int r = w - NG;
        const float* h = g_cell_h + (size_t)r * 64;
        float v0 = h[lane], v1 = h[lane + 32];
        float d1 = warp_dot(v0, v1, a_cc, lane);
        float d2 = warp_dot(v0, v1, a_cc + 64, lane);
        float d3 = warp_dot(v0, v1, a_gc + 64, lane);
        float d4 = warp_dot(v0, v1, a_cg, lane);
        float dg = warp_dot(v0, v1, Wc, lane);
        if (lane == 0) {
            g_e_cc1[r] = make_float2(expf(d1), expf(ALPHA * d1));
            g_e_cc2[r] = make_float2(expf(d2), expf(ALPHA * d2));
            g_e_gc2[r] = make_float2(expf(d3), expf(ALPHA * d3));
            g_e_cg1[r] = make_float2(expf(d4), expf(ALPHA * d4));
            g_gam_c[r] = 1.0f / (1.0f + expf(-(dg + bc[0])));
        }
    }
}

// per-tile register prefetch: adjacency int4 rows + dst exp pairs
__device__ __forceinline__ void load_ae(bool trans, const int* __restrict__ adj,
                                        const float2* __restrict__ e2,
                                        int i0, int j0, int rs,
                                        int r0, int c0,
                                        int4 adjv[4], float4 e2v[2]) {
    if (!trans) {
#pragma unroll
        for (int rr = 0; rr < 4; rr++)
            adjv[rr] = __ldcs((const int4*)&adj[(size_t)(i0 + r0 + rr) * rs + j0 + c0]);
    } else {
#pragma unroll
        for (int cc = 0; cc < 4; cc++)
            adjv[cc] = __ldcs((const int4*)&adj[(size_t)(j0 + c0 + cc) * rs + i0 + r0]);
    }
    e2v[0] = *(const float4*)&e2[j0 + c0];
    e2v[1] = *(const float4*)&e2[j0 + c0 + 2];
}

// ---------------- fused relation kernel ----------------
// 576 blocks: [0,256) gg | [256,384) gc | [384,448) cc | [448,576) cg (transposed)
__global__ __launch_bounds__(256, 2) void rel_kernel(const int* __restrict__ gadj,
                                                     const int* __restrict__ cadj,
                                                     const int* __restrict__ gca) {
    __shared__ __nv_bfloat16 pshb[2][64 * 72];   // P [row][jj]
    __shared__ __nv_bfloat16 hshb[2][72 * 72];   // H^T [n-row][jj]; rows 64..71 ones/zero

    const int b = blockIdx.x;
    const float2 *e1, *e2;
    const __nv_bfloat16* hTb;
    const int* adj;
    float *Nout, *lout;
    int i0, j0base, rs, Ndst;
    bool trans = false;
    if (b < 256) {
        i0 = (b >> 1) * 64; j0base = (b & 1) * 4096;
        e1 = g_e_gg1; e2 = g_e_gg2; hTb = g_gene_hTb; adj = gadj; rs = NG; Ndst = NG;
        Nout = (b & 1) ? g_Ngg1 : g_Ngg0; lout = (b & 1) ? g_lgg1 : g_lgg0;
    } else if (b < 384) {
        i0 = (b - 256) * 64; j0base = 0;
        e1 = g_e_gc1; e2 = g_e_gc2; hTb = g_cell_hTb; adj = gca; rs = NC; Ndst = NC;
        Nout = g_Ngc; lout = g_lgc;
    } else if (b < 448) {
        i0 = (b - 384) * 64; j0base = 0;
        e1 = g_e_cc1; e2 = g_e_cc2; hTb = g_cell_hTb; adj = cadj; rs = NC; Ndst = NC;
        Nout = g_Ncc; lout = g_lcc;
    } else {
        const int bb = b - 448;
        i0 = (bb >> 1) * 64; j0base = (bb & 1) * 4096;
        e1 = g_e_cg1; e2 = g_e_cg2; hTb = g_gene_hTb; adj = gca; rs = NC; Ndst = NG;
        trans = true;
        Nout = (bb & 1) ? g_Ncg1 : g_Ncg0; lout = (bb & 1) ? g_lcg1 : g_lcg0;
    }

    const int tid = threadIdx.x;
    const int tx = tid & 15, ty = tid >> 4;
    const int r0 = ty * 4, c0 = tx * 4;
    const int lane = tid & 31, wid = tid >> 5;
    const int rw = (wid & 3) * 16;
    const int wgrp = wid >> 2;            // 0: n=[0,40), 1: n=[40,72)

    // hoisted src-side exp pairs (fp32)
    float E1p[4], E1n[4];
#pragma unroll
    for (int rr = 0; rr < 4; rr++) {
        float2 v = e1[i0 + r0 + rr];
        E1p[rr] = v.x; E1n[rr] = v.y;
    }

    // ones/zero rows 64..71 in both h buffers (row 64 = 1.0 -> denominator column)
    {
        const __nv_bfloat16 onev = __float2bfloat16(1.f);
        const __nv_bfloat16 zerov = __float2bfloat16(0.f);
        for (int s = tid; s < 8 * 72; s += 256) {
            int r = 64 + s / 72, j = s % 72;
            __nv_bfloat16 v = (r == 64) ? onev : zerov;
            hshb[0][r * 72 + j] = v;
            hshb[1][r * 72 + j] = v;
        }
    }

    const int d1 = tid >> 3, ch1 = tid & 7;
    const int d2 = d1 + 32;
    // prologue: h(0) via cp.async
    CP16((unsigned)__cvta_generic_to_shared(&hshb[0][d1 * 72 + ch1 * 8]),
         &hTb[(size_t)d1 * Ndst + j0base + ch1 * 8]);
    CP16((unsigned)__cvta_generic_to_shared(&hshb[0][d2 * 72 + ch1 * 8]),
         &hTb[(size_t)d2 * Ndst + j0base + ch1 * 8]);
    CP_COMMIT();

    int4 adjv[4]; float4 e2v[2];
    load_ae(trans, adj, e2, i0, j0base, rs, r0, c0, adjv, e2v);

    float cacc[5][4];
#pragma unroll
    for (int nb = 0; nb < 5; nb++)
#pragma unroll
        for (int q = 0; q < 4; q++) cacc[nb][q] = 0.f;

    for (int jt = 0; jt < 64; jt++) {
        const int buf = jt & 1;

        // ---- score (fp32) -> bf16 P tile ----
        float E2p[4], E2n[4];
        E2p[0] = e2v[0].x; E2n[0] = e2v[0].y; E2p[1] = e2v[0].z; E2n[1] = e2v[0].w;
        E2p[2] = e2v[1].x; E2n[2] = e2v[1].y; E2p[3] = e2v[1].z; E2n[3] = e2v[1].w;
#pragma unroll
        for (int rr = 0; rr < 4; rr++) {
            float pv[4];
#pragma unroll
            for (int cc = 0; cc < 4; cc++) {
                int a = trans ? ((const int*)&adjv[cc])[rr]
                              : ((const int*)&adjv[rr])[cc];
                float q = E1p[rr] * E2p[cc];
                float p = (q >= 1.f) ? q : E1n[rr] * E2n[cc];
                p = (a > 0) ? p : 0.f;
                pv[cc] = p;
            }
            *(uint2*)&pshb[buf][(r0 + rr) * 72 + c0] =
                make_uint2(bf16x2(pv[0], pv[1]), bf16x2(pv[2], pv[3]));
        }

        // register prefetch of next tile's adjacency + e2
        const int j0n = j0base + ((jt < 63) ? (jt + 1) : 0) * 64;
        int4 adjn[4]; float4 e2n2[2];
        load_ae(trans, adj, e2, i0, j0n, rs, r0, c0, adjn, e2n2);

        CP_WAIT0();          // h(jt) landed
        __syncthreads();     // P tile visible; everyone past mma(jt-1)

        // issue h(jt+1) into the other buffer (overlaps mma + next score)
        if (jt < 63) {
            const int jh = j0base + (jt + 1) * 64;
            CP16((unsigned)__cvta_generic_to_shared(&hshb[buf ^ 1][d1 * 72 + ch1 * 8]),
                 &hTb[(size_t)d1 * Ndst + jh + ch1 * 8]);
            CP16((unsigned)__cvta_generic_to_shared(&hshb[buf ^ 1][d2 * 72 + ch1 * 8]),
                 &hTb[(size_t)d2 * Ndst + jh + ch1 * 8]);
            CP_COMMIT();
        }

        // ---- P @ [H; ones] via HMMA ----
        unsigned afr[4][4];
#pragma unroll
        for (int ks = 0; ks < 4; ks++)
            ldsm4(afr[ks], &pshb[buf][(rw + (lane & 15)) * 72 + ks * 16 + (lane >> 4) * 8]);
        if (wgrp == 0) {
#pragma unroll
            for (int nb = 0; nb < 5; nb++) {
                unsigned b0[4], b1f[4];
                const int nrow = nb * 8 + (lane & 7);
                ldsm4(b0, &hshb[buf][nrow * 72 + (lane >> 3) * 8]);
                ldsm4(b1f, &hshb[buf][nrow * 72 + 32 + (lane >> 3) * 8]);
                mma16816(cacc[nb], afr[0], b0[0], b0[1]);
                mma16816(cacc[nb], afr[1], b0[2], b0[3]);
                mma16816(cacc[nb], afr[2], b1f[0], b1f[1]);
                mma16816(cacc[nb], afr[3], b1f[2], b1f[3]);
            }
        } else {
#pragma unroll
            for (int nb = 0; nb < 4; nb++) {
                unsigned b0[4], b1f[4];
                const int nrow = 40 + nb * 8 + (lane & 7);
                ldsm4(b0, &hshb[buf][nrow * 72 + (lane >> 3) * 8]);
                ldsm4(b1f, &hshb[buf][nrow * 72 + 32 + (lane >> 3) * 8]);
                mma16816(cacc[nb], afr[0], b0[0], b0[1]);
                mma16816(cacc[nb], afr[1], b0[2], b0[3]);
                mma16816(cacc[nb], afr[2], b1f[0], b1f[1]);
                mma16816(cacc[nb], afr[3], b1f[2], b1f[3]);
            }
        }

#pragma unroll
        for (int rr = 0; rr < 4; rr++) adjv[rr] = adjn[rr];
        e2v[0] = e2n2[0]; e2v[1] = e2n2[1];
    }

    // ---- epilogue: store N (cols 0..63) and l (ones column = col 64) ----
    const int crow = i0 + rw + (lane >> 2);
    if (wgrp == 0) {
#pragma unroll
        for (int nb = 0; nb < 5; nb++) {
            const int d = nb * 8 + 2 * (lane & 3);
            *(float2*)&Nout[(size_t)crow * 64 + d] = make_float2(cacc[nb][0], cacc[nb][1]);
            *(float2*)&Nout[(size_t)(crow + 8) * 64 + d] = make_float2(cacc[nb][2], cacc[nb][3]);
        }
    } else {
#pragma unroll
        for (int nb = 0; nb < 3; nb++) {
            const int d = 40 + nb * 8 + 2 * (lane & 3);
            *(float2*)&Nout[(size_t)crow * 64 + d] = make_float2(cacc[nb][0], cacc[nb][1]);
            *(float2*)&Nout[(size_t)(crow + 8) * 64 + d] = make_float2(cacc[nb][2], cacc[nb][3]);
        }
        if ((lane & 3) == 0) {           // col 64 = denominator
            lout[crow] = cacc[3][0];
            lout[crow + 8] = cacc[3][2];
        }
    }
}

// ---------------- final combine ----------------
__global__ void combine_kernel(float* __restrict__ out) {
    const int idx4 = blockIdx.x * blockDim.x + threadIdx.x;
    const int e = idx4 * 4;
    if (e < NG * 64) {
        const int i = e >> 6;
        const float lg = g_lgg0[i] + g_lgg1[i];
        const float invgg = lg > 0.f ? 1.0f / lg : 0.f;
        const float lc = g_lgc[i];
        const float invgc = lc > 0.f ? 1.0f / lc : 0.f;
        const float ga = g_gam_g[i];
        float4 h = *(float4*)&g_gene_h[e];
        float4 A0 = *(float4*)&g_Ngg0[e];
        float4 A1 = *(float4*)&g_Ngg1[e];
        float4 B = *(float4*)&g_Ngc[e];
        float4 o;
        o.x = leaky(h.x + (A0.x + A1.x) * invgg + ga * B.x * invgc);
        o.y = leaky(h.y + (A0.y + A1.y) * invgg + ga * B.y * invgc);
        o.z = leaky(h.z + (A0.z + A1.z) * invgg + ga * B.z * invgc);
        o.w = leaky(h.w + (A0.w + A1.w) * invgg + ga * B.w * invgc);
        *(float4*)&out[e] = o;
    } else if (e < (NG + NC) * 64) {
        const int e2 = e - NG * 64;
        const int i = e2 >> 6;
        const float lcc_ = g_lcc[i];
        const float invcc = lcc_ > 0.f ? 1.0f / lcc_ : 0.f;
        const float lcg_ = g_lcg0[i] + g_lcg1[i];
        const float invcg = lcg_ > 0.f ? 1.0f / lcg_ : 0.f;
        const float gc_ = g_gam_c[i];
        float4 h = *(float4*)&g_cell_h[e2];
        float4 A = *(float4*)&g_Ncc[e2];
        float4 B0 = *(float4*)&g_Ncg0[e2];
        float4 B1 = *(float4*)&g_Ncg1[e2];
        float4 o;
        o.x = leaky(h.x + A.x * invcc + gc_ * (B0.x + B1.x) * invcg);
        o.y = leaky(h.y + A.y * invcc + gc_ * (B0.y + B1.y) * invcg);
        o.z = leaky(h.z + A.z * invcc + gc_ * (B0.z + B1.z) * invcg);
        o.w = leaky(h.w + A.w * invcc + gc_ * (B0.w + B1.w) * invcg);
        *(float4*)&out[e] = o;
    }
}

// ---------------- launch ----------------
extern "C" void kernel_launch(void* const* d_in, const int* in_sizes, int n_in,
                              void* d_out, int out_size) {
    const float* gene_x  = (const float*)d_in[0];
    const float* cell_x  = (const float*)d_in[1];
    const float* W_g     = (const float*)d_in[2];
    const float* W_c     = (const float*)d_in[3];
    const float* a_gg    = (const float*)d_in[4];
    const float* a_gc    = (const float*)d_in[5];
    const float* a_cc    = (const float*)d_in[6];
    const float* a_cg    = (const float*)d_in[7];
    const float* Wgate_g = (const float*)d_in[8];
    const float* bgate_g = (const float*)d_in[9];
    const float* Wgate_c = (const float*)d_in[10];
    const float* bgate_c = (const float*)d_in[11];
    const int* gene_adj  = (const int*)d_in[12];
    const int* cell_adj  = (const int*)d_in[13];
    const int* gca       = (const int*)d_in[14];
    float* out = (float*)d_out;

    gemm64_kernel<<<NG / 16, 256>>>(gene_x, W_g, FGk, 0);
    gemm64_kernel<<<NC / 16, 256>>>(cell_x, W_c, FCk, 1);
    svec_kernel<<<(NG + NC) / 8, 256>>>(a_gg, a_gc, a_cc, a_cg,
                                        Wgate_g, bgate_g, Wgate_c, bgate_c);
    rel_kernel<<<576, 256>>>(gene_adj, cell_adj, gca);
    combine_kernel<<<((NG + NC) * 64 / 4) / 256, 256>>>(out);
}